// round 1
// baseline (speedup 1.0000x reference)
#include <cuda_runtime.h>

// Custom_Decoder: est = einsum('bcle,we->bclw', x, wt) then overlap_and_add(step=8)
// B=8, C=2, FRAMES=3999, E=512, W=16, STEP=8 -> out [8,2,32000] fp32
//
// Fused formulation: out[bc, 16p + (0..7)]  = x[2p]  . wt[0..8)  + x[2p-1] . wt[8..16)
//                    out[bc, 16p + (8..15)] = x[2p+1]. wt[0..8)  + x[2p]   . wt[8..16)
// (boundary frames -1 and 3999 contribute zero)

#define FRAMES 3999
#define E_DIM 512
#define W_DIM 16
#define N_BC 16
#define PAIRS 2000          // per (b,c): 2000 pairs * 16 samples = 32000
#define OUT_T 32000
#define KS 8                // k-split lanes per pair
#define PAIRS_PER_BLOCK 32
#define NTHREADS 256        // 32 pairs * 8 ks lanes

typedef unsigned long long ull;

__device__ __forceinline__ void ffma2(ull &d, ull a, ull b) {
    // packed 2xfp32 FMA (Blackwell FFMA2) — only reachable via PTX
    asm("fma.rn.f32x2 %0, %1, %2, %0;" : "+l"(d) : "l"(a), "l"(b));
}

__global__ __launch_bounds__(NTHREADS)
void decoder_oadd_kernel(const float* __restrict__ x,
                         const float* __restrict__ wt,
                         float* __restrict__ out)
{
    __shared__ __align__(16) float wsm[W_DIM * E_DIM];   // 32 KB

    const int tid = threadIdx.x;

    // stage weight into smem (coalesced float4)
#pragma unroll
    for (int j = 0; j < (W_DIM * E_DIM) / (4 * NTHREADS); j++) {
        int idx = (j * NTHREADS + tid) * 4;
        *(float4*)(wsm + idx) = *(const float4*)(wt + idx);
    }
    __syncthreads();

    const int ks     = tid & (KS - 1);   // 0..7 : which K slice
    const int plocal = tid >> 3;         // 0..31: which output pair in block
    const int P  = blockIdx.x * PAIRS_PER_BLOCK + plocal;  // 0..31999
    const int bc = P / PAIRS;
    const int p  = P - bc * PAIRS;

    const float* base = x + (size_t)bc * FRAMES * E_DIM + (size_t)(2 * p) * E_DIM;
    // view frames as 16-byte (2x fp32-pair) vectors
    const ulonglong2* __restrict__ pB = (const ulonglong2*)(base);           // frame 2p   (always valid)
    const ulonglong2* __restrict__ pA = (const ulonglong2*)(base - E_DIM);   // frame 2p-1
    const ulonglong2* __restrict__ pC = (const ulonglong2*)(base + E_DIM);   // frame 2p+1
    const bool vA = (p > 0);             // frame 2p-1 exists
    const bool vC = (p < PAIRS - 1);     // frame 2p+1 <= 3998

    // 16 packed accumulators: a0[r] -> out sample 16p+r, a1[r] -> out sample 16p+8+r
    ull a0[8], a1[8];
#pragma unroll
    for (int r = 0; r < 8; r++) { a0[r] = 0ULL; a1[r] = 0ULL; }

    // Each lane covers K elements {32*i + 4*ks + (0..3)}, i = 0..15.
    // The 8 ks-lanes of one pair thus read one contiguous 128B line per frame
    // per iteration (coalesced LDG, conflict-free broadcast-ish LDS).
#pragma unroll 4
    for (int i = 0; i < 16; i++) {
        const int off = i * 32 + ks * 4;     // float index within frame / weight row
        const int v   = off >> 2;            // 16B-vector index

        ulonglong2 aB = pB[v];
        ulonglong2 aA = vA ? pA[v] : make_ulonglong2(0ULL, 0ULL);
        ulonglong2 aC = vC ? pC[v] : make_ulonglong2(0ULL, 0ULL);

#pragma unroll
        for (int r = 0; r < 8; r++) {
            ulonglong2 wl = *(const ulonglong2*)(wsm + r * E_DIM + off);        // wt[r]
            ulonglong2 wh = *(const ulonglong2*)(wsm + (r + 8) * E_DIM + off);  // wt[r+8]
            ffma2(a0[r], aB.x, wl.x);
            ffma2(a0[r], aB.y, wl.y);
            ffma2(a0[r], aA.x, wh.x);
            ffma2(a0[r], aA.y, wh.y);
            ffma2(a1[r], aC.x, wl.x);
            ffma2(a1[r], aC.y, wl.y);
            ffma2(a1[r], aB.x, wh.x);
            ffma2(a1[r], aB.y, wh.y);
        }
    }

    // horizontal (even/odd-k) add, then reduce over the 8 ks lanes
    float s[16];
#pragma unroll
    for (int r = 0; r < 8; r++) {
        s[r]     = __uint_as_float((unsigned)(a0[r] & 0xffffffffu)) +
                   __uint_as_float((unsigned)(a0[r] >> 32));
        s[8 + r] = __uint_as_float((unsigned)(a1[r] & 0xffffffffu)) +
                   __uint_as_float((unsigned)(a1[r] >> 32));
    }
#pragma unroll
    for (int m = 1; m <= 4; m <<= 1) {
#pragma unroll
        for (int j = 0; j < 16; j++)
            s[j] += __shfl_xor_sync(0xffffffffu, s[j], m);
    }

    if (ks == 0) {
        float* o = out + (size_t)bc * OUT_T + (size_t)p * 16;
        *(float4*)(o)      = make_float4(s[0],  s[1],  s[2],  s[3]);
        *(float4*)(o + 4)  = make_float4(s[4],  s[5],  s[6],  s[7]);
        *(float4*)(o + 8)  = make_float4(s[8],  s[9],  s[10], s[11]);
        *(float4*)(o + 12) = make_float4(s[12], s[13], s[14], s[15]);
    }
}

extern "C" void kernel_launch(void* const* d_in, const int* in_sizes, int n_in,
                              void* d_out, int out_size)
{
    // robust input identification: dec_input is the big one (32,759,808 elems),
    // weight is 8192 elems
    const float* x;
    const float* wt;
    if (in_sizes[0] > in_sizes[1]) { x = (const float*)d_in[0]; wt = (const float*)d_in[1]; }
    else                           { x = (const float*)d_in[1]; wt = (const float*)d_in[0]; }

    const int total_pairs = N_BC * PAIRS;                 // 32000
    const int grid = total_pairs / PAIRS_PER_BLOCK;       // 1000 blocks
    decoder_oadd_kernel<<<grid, NTHREADS>>>(x, wt, (float*)d_out);
}

// round 3
// speedup vs baseline: 1.2087x; 1.2087x over previous
#include <cuda_runtime.h>

// Custom_Decoder: est = einsum('bcle,we->bclw', x, wt) then overlap_and_add(step=8)
// B=8, C=2, FRAMES=3999, E=512, W=16, STEP=8 -> out [8,2,32000] fp32
//
// Fused formulation: out[bc, 16p + (0..7)]  = x[2p]  . wt[0..8)  + x[2p-1] . wt[8..16)
//                    out[bc, 16p + (8..15)] = x[2p+1]. wt[0..8)  + x[2p]   . wt[8..16)
// (boundary frames -1 and 3999 contribute zero)

#define FRAMES 3999
#define E_DIM 512
#define W_DIM 16
#define N_BC 16
#define PAIRS 2000          // per (b,c): 2000 pairs * 16 samples = 32000
#define OUT_T 32000
#define KS 8                // k-split lanes per pair
#define PAIRS_PER_BLOCK 32
#define NTHREADS 256        // 32 pairs * 8 ks lanes

typedef unsigned long long ull;

__device__ __forceinline__ void ffma2(ull &d, ull a, ull b) {
    // packed 2xfp32 FMA (Blackwell FFMA2) — only reachable via PTX
    asm("fma.rn.f32x2 %0, %1, %2, %0;" : "+l"(d) : "l"(a), "l"(b));
}

__global__ __launch_bounds__(NTHREADS, 4)   // cap regs at 64 -> 4 CTAs/SM (50% occ)
void decoder_oadd_kernel(const float* __restrict__ x,
                         const float* __restrict__ wt,
                         float* __restrict__ out)
{
    __shared__ __align__(16) float wsm[W_DIM * E_DIM];   // 32 KB

    const int tid = threadIdx.x;

    // stage weight into smem (coalesced float4)
#pragma unroll
    for (int j = 0; j < (W_DIM * E_DIM) / (4 * NTHREADS); j++) {
        int idx = (j * NTHREADS + tid) * 4;
        *(float4*)(wsm + idx) = *(const float4*)(wt + idx);
    }
    __syncthreads();

    const int ks     = tid & (KS - 1);   // 0..7 : which K slice
    const int plocal = tid >> 3;         // 0..31: which output pair in block
    const int P  = blockIdx.x * PAIRS_PER_BLOCK + plocal;  // 0..31999
    const int bc = P / PAIRS;
    const int p  = P - bc * PAIRS;

    const float* base = x + (size_t)bc * FRAMES * E_DIM + (size_t)(2 * p) * E_DIM;
    // view frames as 16-byte (2x fp32-pair) vectors
    const ulonglong2* __restrict__ pB = (const ulonglong2*)(base);           // frame 2p   (always valid)
    const ulonglong2* __restrict__ pA = (const ulonglong2*)(base - E_DIM);   // frame 2p-1
    const ulonglong2* __restrict__ pC = (const ulonglong2*)(base + E_DIM);   // frame 2p+1
    const bool vA = (p > 0);             // frame 2p-1 exists
    const bool vC = (p < PAIRS - 1);     // frame 2p+1 <= 3998

    // 16 packed accumulators: a0[r] -> out sample 16p+r, a1[r] -> out sample 16p+8+r
    ull a0[8], a1[8];
#pragma unroll
    for (int r = 0; r < 8; r++) { a0[r] = 0ULL; a1[r] = 0ULL; }

    // Each lane covers K elements {32*i + 4*ks + (0..3)}, i = 0..15.
    // The 8 ks-lanes of one pair read one contiguous 128B line per frame per
    // iteration (coalesced LDG, conflict-free broadcast LDS).
    // Full unroll: let ptxas front-batch LDGs (MLP ~16) instead of stalling at
    // every unroll-4 boundary.
#pragma unroll
    for (int i = 0; i < 16; i++) {
        const int off = i * 32 + ks * 4;     // float index within frame / weight row
        const int v   = off >> 2;            // 16B-vector index

        ulonglong2 aB = pB[v];
        ulonglong2 aA = vA ? pA[v] : make_ulonglong2(0ULL, 0ULL);
        ulonglong2 aC = vC ? pC[v] : make_ulonglong2(0ULL, 0ULL);

#pragma unroll
        for (int r = 0; r < 8; r++) {
            ulonglong2 wl = *(const ulonglong2*)(wsm + r * E_DIM + off);        // wt[r]
            ulonglong2 wh = *(const ulonglong2*)(wsm + (r + 8) * E_DIM + off);  // wt[r+8]
            ffma2(a0[r], aB.x, wl.x);
            ffma2(a0[r], aB.y, wl.y);
            ffma2(a0[r], aA.x, wh.x);
            ffma2(a0[r], aA.y, wh.y);
            ffma2(a1[r], aC.x, wl.x);
            ffma2(a1[r], aC.y, wl.y);
            ffma2(a1[r], aB.x, wh.x);
            ffma2(a1[r], aB.y, wh.y);
        }
    }

    // horizontal (even/odd-k) add, then reduce over the 8 ks lanes
    float s[16];
#pragma unroll
    for (int r = 0; r < 8; r++) {
        s[r]     = __uint_as_float((unsigned)(a0[r] & 0xffffffffu)) +
                   __uint_as_float((unsigned)(a0[r] >> 32));
        s[8 + r] = __uint_as_float((unsigned)(a1[r] & 0xffffffffu)) +
                   __uint_as_float((unsigned)(a1[r] >> 32));
    }
#pragma unroll
    for (int m = 1; m <= 4; m <<= 1) {
#pragma unroll
        for (int j = 0; j < 16; j++)
            s[j] += __shfl_xor_sync(0xffffffffu, s[j], m);
    }

    if (ks == 0) {
        float* o = out + (size_t)bc * OUT_T + (size_t)p * 16;
        *(float4*)(o)      = make_float4(s[0],  s[1],  s[2],  s[3]);
        *(float4*)(o + 4)  = make_float4(s[4],  s[5],  s[6],  s[7]);
        *(float4*)(o + 8)  = make_float4(s[8],  s[9],  s[10], s[11]);
        *(float4*)(o + 12) = make_float4(s[12], s[13], s[14], s[15]);
    }
}

extern "C" void kernel_launch(void* const* d_in, const int* in_sizes, int n_in,
                              void* d_out, int out_size)
{
    // dec_input is the big input (32,759,808 elems), weight is 8192 elems
    const float* x;
    const float* wt;
    if (in_sizes[0] > in_sizes[1]) { x = (const float*)d_in[0]; wt = (const float*)d_in[1]; }
    else                           { x = (const float*)d_in[1]; wt = (const float*)d_in[0]; }

    const int total_pairs = N_BC * PAIRS;                 // 32000
    const int grid = total_pairs / PAIRS_PER_BLOCK;       // 1000 blocks
    decoder_oadd_kernel<<<grid, NTHREADS>>>(x, wt, (float*)d_out);
}